// round 6
// baseline (speedup 1.0000x reference)
#include <cuda_runtime.h>

// ProteinCRF: batched linear-chain CRF NLL.  B=2048, L=2048, T=8.
//
// d_in[0] emissions  f32 [B,L,T]
// d_in[1] transitions f32 [T,T]
// d_in[2] start_transitions f32 [T]
// d_in[3] end_transitions   f32 [T]
// d_in[4] tags int64-or-int32 [B,L]  (0=pad, 1..T) -- width detected on device
// out: scalar f32 = mean(denom - num)
//
// R6 vs R5 (175us): scan loop was issue/MIO bound (~30 instr, 9 SHFL/step).
//  * numerator + length computed in a parallel per-block PREPASS (lane-strided
//    over t, butterfly reduce) -> scan loop has NO tags, NO LDS, NO num shfl
//  * scan loop: 8 shfl + 8 fma + add + mul + 1 sel (+ amortized ldg/mufu/renorm)
//  * final mean folded into scan kernel via last-block-arrives reduction
//    (deterministic: fixed arithmetic order; counter reset for graph replay)

#define CRF_B 2048
#define CRF_L 2048
#define CRF_T 8
#define BLOCKS (CRF_B * CRF_T / 128)   // 128

__device__ float        g_llh[CRF_B];
__device__ unsigned int g_count = 0;

__global__ __launch_bounds__(128, 1)
void crf_forward_kernel(const float* __restrict__ emissions,
                        const float* __restrict__ transitions,
                        const float* __restrict__ start_tr,
                        const float* __restrict__ end_tr,
                        const int*   __restrict__ tagsw,   // 32-bit word view
                        float*       __restrict__ out)
{
    __shared__ float s_trans[CRF_T * CRF_T];
    __shared__ float s_start[CRF_T];
    __shared__ float s_end[CRF_T];
    __shared__ float sm_num[16];
    __shared__ int   sm_len[16];
    __shared__ bool  sm_last;

    const int tid = threadIdx.x;
    if (tid < 64)              s_trans[tid]      = transitions[tid];
    if (tid >= 64 && tid < 72) s_start[tid - 64] = start_tr[tid - 64];
    if (tid >= 72 && tid < 80) s_end[tid - 72]   = end_tr[tid - 72];
    __syncthreads();

    // tags int64 vs int32: lengths >= L/2 so tags[0][1] != 0. If int64 (LE),
    // word #1 is the high half of element 0 -> 0; if int32 it's nonzero.
    const int tstride = (tagsw[1] == 0) ? 2 : 1;

    const int lane = tid & 31;
    const int wid  = tid >> 5;
    const int blockbase = blockIdx.x * 16;

    // ================= PREPASS: numerator + length, lane-parallel over t ====
    // Warp w handles batches blockbase + 4w .. 4w+3 (matches scan mapping).
    for (int bl = 0; bl < 4; bl++) {
        const int batch = blockbase + wid * 4 + bl;
        const int*   tg = tagsw + (size_t)batch * CRF_L * tstride;
        const float* em = emissions + (size_t)batch * (CRF_L * CRF_T);

        float s   = 0.0f;
        int   cnt = 0;
        for (int it = 0; it < CRF_L / 32; it++) {
            const int t   = it * 32 + lane;
            const int tag = tg[t * tstride];
            int ptag = __shfl_up_sync(0xFFFFFFFFu, tag, 1);
            if (lane == 0 && it > 0) ptag = tg[(t - 1) * tstride];

            const bool valid = (tag != 0);
            cnt += valid;
            const int cur = tag - 1;
            if (t == 0) {
                s += s_start[cur] + em[cur];
            } else if (valid) {
                s += s_trans[(ptag - 1) * CRF_T + cur] + em[t * CRF_T + cur];
            }
        }
        // butterfly reduce s (order fixed -> deterministic) and cnt
#pragma unroll
        for (int off = 16; off > 0; off >>= 1) {
            s   += __shfl_xor_sync(0xFFFFFFFFu, s, off);
            cnt += __shfl_xor_sync(0xFFFFFFFFu, cnt, off);
        }
        if (lane == 0) {
            const int last = tg[(cnt - 1) * tstride] - 1;
            sm_num[wid * 4 + bl] = s + s_end[last];
            sm_len[wid * 4 + bl] = cnt;
        }
    }
    __syncthreads();

    // ================= SCAN: exp-domain forward recurrence ==================
    const int j     = lane & 7;                 // my state
    const unsigned gmask = 0xFFu << (lane & 24);
    const int blocal = tid >> 3;                // 0..15
    const int batch  = blockbase + blocal;
    const int len    = sm_len[blocal];

    const float* em_base = emissions + (size_t)batch * (CRF_L * CRF_T);

    // E column j: Ecol[i] = exp(trans[i][j])
    float Ecol[CRF_T];
#pragma unroll
    for (int i = 0; i < CRF_T; i++) Ecol[i] = __expf(s_trans[i * CRF_T + j]);

    // t = 0
    float em0 = em_base[j];
    float a0  = s_start[j] + em0;
    float mx  = a0;
    mx = fmaxf(mx, __shfl_xor_sync(gmask, mx, 1, 8));
    mx = fmaxf(mx, __shfl_xor_sync(gmask, mx, 2, 8));
    mx = fmaxf(mx, __shfl_xor_sync(gmask, mx, 4, 8));
    const float m0 = mx;

    float beta = __expf(a0 - m0);
    int   eacc = 0;

    // prime first chunk of emissions (t = 1..8)
    float emA[8];
#pragma unroll
    for (int k = 0; k < 8; k++) emA[k] = em_base[(1 + k) * CRF_T + j];

    for (int t0 = 1; t0 < len; t0 += 8) {
        // prefetch next chunk (independent LDGs, clamped)
        float emB[8];
#pragma unroll
        for (int k = 0; k < 8; k++) {
            int tt = t0 + 8 + k;
            tt = (tt < CRF_L) ? tt : (CRF_L - 1);
            emB[k] = em_base[tt * CRF_T + j];
        }

        // emission exps for this chunk (off the beta critical path)
        float ex[8];
#pragma unroll
        for (int k = 0; k < 8; k++) ex[k] = __expf(emA[k]);

#pragma unroll
        for (int k = 0; k < 8; k++) {
            const bool act = (t0 + k) < len;

            float b0 = __shfl_sync(gmask, beta, 0, 8);
            float b1 = __shfl_sync(gmask, beta, 1, 8);
            float b2 = __shfl_sync(gmask, beta, 2, 8);
            float b3 = __shfl_sync(gmask, beta, 3, 8);
            float b4 = __shfl_sync(gmask, beta, 4, 8);
            float b5 = __shfl_sync(gmask, beta, 5, 8);
            float b6 = __shfl_sync(gmask, beta, 6, 8);
            float b7 = __shfl_sync(gmask, beta, 7, 8);

            float sA = b0 * Ecol[0];
            float sB = b1 * Ecol[1];
            sA = fmaf(b2, Ecol[2], sA);
            sB = fmaf(b3, Ecol[3], sB);
            sA = fmaf(b4, Ecol[4], sA);
            sB = fmaf(b5, Ecol[5], sB);
            sA = fmaf(b6, Ecol[6], sA);
            sB = fmaf(b7, Ecol[7], sB);

            float u = (sA + sB) * ex[k];

            // renorm 2x per chunk from already-gathered previous betas
            if (k == 3 || k == 7) {
                float m = fmaxf(fmaxf(fmaxf(b0, b1), fmaxf(b2, b3)),
                                fmaxf(fmaxf(b4, b5), fmaxf(b6, b7)));
                int e = ((__float_as_int(m) >> 23) & 0xFF) - 127;
                u *= __int_as_float((127 - e) << 23);   // u * 2^-e
                if (act) eacc += e;
            }

            if (act) beta = u;
        }

#pragma unroll
        for (int k = 0; k < 8; k++) emA[k] = emB[k];
    }

    // denom = m0 + eacc*ln2 + log( sum_j beta_j * exp(end_j) )
    float w = beta * __expf(s_end[j]);
    w += __shfl_xor_sync(gmask, w, 1, 8);
    w += __shfl_xor_sync(gmask, w, 2, 8);
    w += __shfl_xor_sync(gmask, w, 4, 8);

    const float denom = m0 + (float)eacc * 0.693147180559945309f + __logf(w);

    if (j == 0) g_llh[batch] = denom - sm_num[blocal];

    // ================= last-block-arrives final mean ========================
    __syncthreads();
    __threadfence();
    if (tid == 0) {
        unsigned old = atomicAdd(&g_count, 1u);
        sm_last = (old == (unsigned)(BLOCKS - 1));
    }
    __syncthreads();

    if (sm_last) {
        __shared__ double sh[4];
        double s = 0.0;
        for (int i = tid; i < CRF_B; i += 128) s += (double)__ldcg(&g_llh[i]);
#pragma unroll
        for (int off = 16; off > 0; off >>= 1)
            s += __shfl_xor_sync(0xFFFFFFFFu, s, off);
        if (lane == 0) sh[wid] = s;
        __syncthreads();
        if (tid == 0) {
            out[0] = (float)((sh[0] + sh[1] + sh[2] + sh[3]) / (double)CRF_B);
            g_count = 0;   // reset for graph replay
        }
    }
}

extern "C" void kernel_launch(void* const* d_in, const int* in_sizes, int n_in,
                              void* d_out, int out_size)
{
    const float* emissions   = (const float*)d_in[0];
    const float* transitions = (const float*)d_in[1];
    const float* start_tr    = (const float*)d_in[2];
    const float* end_tr      = (const float*)d_in[3];
    const int*   tagsw       = (const int*)d_in[4];

    crf_forward_kernel<<<BLOCKS, 128>>>(
        emissions, transitions, start_tr, end_tr, tagsw, (float*)d_out);
}